// round 14
// baseline (speedup 1.0000x reference)
#include <cuda_runtime.h>
#include <cuda_bf16.h>
#include <math.h>

#define MAXN 50000
#define MAXE 600000
#define HID 128
#define NGRAPH 64

// ---------------- scratch (static device globals) ----------------
__device__ __nv_bfloat16 g_xb[(size_t)MAXN * HID];
__device__ __nv_bfloat16 g_yb[(size_t)MAXN * HID];
__device__ __nv_bfloat16 g_h0b[(size_t)MAXN * HID];
__device__ __nv_bfloat16 g_aggb[(size_t)MAXN * HID];
__device__ float g_part[(size_t)MAXN * HID];       // fp32 partial (x@W2 / h0@W2)
__device__ int   g_cnt[MAXN + 1];
__device__ int   g_off[MAXN + 1];
__device__ int   g_fill[MAXN];
__device__ int   g_srcs[MAXE];
__device__ int   g_bsum[64];
__device__ float g_pooled[NGRAPH * HID];
__device__ __nv_bfloat16 g_wt[128 * 768];
// wt regions (each 128n x 128k, [n][k]):
// 0: lin_w0 | 16384: agg_w0 k<128 | 32768: agg_w0 k>=128
// 49152: lin_w1 | 65536: agg_w1 k<128 | 81920: agg_w1 k>=128

// ---------------- tiny helpers ----------------
__device__ __forceinline__ void cpa16(unsigned dst, const void* src, int pbytes) {
    asm volatile("cp.async.cg.shared.global [%0], [%1], 16, %2;\n"
                 :: "r"(dst), "l"(src), "r"(pbytes));
}
__device__ __forceinline__ void cpa_commit() { asm volatile("cp.async.commit_group;\n"); }
__device__ __forceinline__ void cpa_wait0()  { asm volatile("cp.async.wait_group 0;\n"); }

__device__ __forceinline__ void mma16816(float c[4], const unsigned a[4], const unsigned* b) {
    asm volatile(
        "mma.sync.aligned.m16n8k16.row.col.f32.bf16.bf16.f32 "
        "{%0,%1,%2,%3},{%4,%5,%6,%7},{%8,%9},{%0,%1,%2,%3};"
        : "+f"(c[0]), "+f"(c[1]), "+f"(c[2]), "+f"(c[3])
        : "r"(a[0]), "r"(a[1]), "r"(a[2]), "r"(a[3]), "r"(b[0]), "r"(b[1]));
}
__device__ __forceinline__ void ldsm_x4(unsigned r[4], unsigned addr) {
    asm volatile("ldmatrix.sync.aligned.m8n8.x4.shared.b16 {%0,%1,%2,%3}, [%4];"
                 : "=r"(r[0]), "=r"(r[1]), "=r"(r[2]), "=r"(r[3]) : "r"(addr));
}

// ---------------- conversion kernels ----------------
__global__ void wconvert_all(const float* __restrict__ w0, const float* __restrict__ wa0,
                             const float* __restrict__ w1, const float* __restrict__ wa1,
                             __nv_bfloat16* __restrict__ wt)
{
    const int r = blockIdx.y;
    const int K = (r & 1) ? 256 : 128;
    const float* W = (r == 0) ? w0 : (r == 1) ? wa0 : (r == 2) ? w1 : wa1;
    int idx = blockIdx.x * blockDim.x + threadIdx.x;
    if (idx >= 128 * K) return;
    int n = idx / K, k = idx % K;
    __nv_bfloat16 v = __float2bfloat16(W[(size_t)k * 128 + n]);
    int dst;
    if (r == 0)      dst = n * 128 + k;
    else if (r == 2) dst = 49152 + n * 128 + k;
    else {
        int base = (r == 1) ? 16384 : 65536;
        if (k < 128) dst = base + n * 128 + k;
        else         dst = base + 16384 + n * 128 + (k - 128);
    }
    wt[dst] = v;
}

__global__ void xconvert_kernel(const float* __restrict__ x,
                                __nv_bfloat16* __restrict__ xb, int total4)
{
    int i = blockIdx.x * blockDim.x + threadIdx.x;
    if (i >= total4) return;
    float4 v = *(const float4*)(x + (size_t)i * 4);
    __nv_bfloat162 p0(__float2bfloat16(v.x), __float2bfloat16(v.y));
    __nv_bfloat162 p1(__float2bfloat16(v.z), __float2bfloat16(v.w));
    *(__nv_bfloat162*)(xb + (size_t)i * 4)     = p0;
    *(__nv_bfloat162*)(xb + (size_t)i * 4 + 2) = p1;
}

// ---------------- CSR build ----------------
__global__ void zero_pool_kernel(float* pooled, int npool) {
    int i = blockIdx.x * blockDim.x + threadIdx.x;
    if (i < npool) pooled[i] = 0.0f;
}
__global__ void zero_cnt_kernel(int* cnt, int ncnt) {
    int i = blockIdx.x * blockDim.x + threadIdx.x;
    if (i < ncnt) cnt[i] = 0;
}
__global__ void hist_kernel(const int* __restrict__ dst, int* __restrict__ cnt, int E) {
    int e = blockIdx.x * blockDim.x + threadIdx.x;
    if (e < E) atomicAdd(&cnt[dst[e]], 1);
}
__global__ void scan1_kernel(const int* __restrict__ cnt, int* __restrict__ bsum, int Ntot) {
    __shared__ int ws[32];
    int i = blockIdx.x * 1024 + threadIdx.x;
    int v = (i < Ntot) ? cnt[i] : 0;
    #pragma unroll
    for (int d = 16; d > 0; d >>= 1) v += __shfl_down_sync(0xffffffffu, v, d);
    if ((threadIdx.x & 31) == 0) ws[threadIdx.x >> 5] = v;
    __syncthreads();
    if (threadIdx.x < 32) {
        int s = ws[threadIdx.x];
        #pragma unroll
        for (int d = 16; d > 0; d >>= 1) s += __shfl_down_sync(0xffffffffu, s, d);
        if (threadIdx.x == 0) bsum[blockIdx.x] = s;
    }
}
__global__ void scan2_kernel(int* __restrict__ bsum, int nb) {
    int tid = threadIdx.x;
    int v0 = (tid < nb) ? bsum[tid] : 0;
    int v1 = (tid + 32 < nb) ? bsum[tid + 32] : 0;
    int x = v0;
    #pragma unroll
    for (int d = 1; d < 32; d <<= 1) {
        int t = __shfl_up_sync(0xffffffffu, x, d);
        if (tid >= d) x += t;
    }
    int total0 = __shfl_sync(0xffffffffu, x, 31);
    int y = v1;
    #pragma unroll
    for (int d = 1; d < 32; d <<= 1) {
        int t = __shfl_up_sync(0xffffffffu, y, d);
        if (tid >= d) y += t;
    }
    if (tid < nb) bsum[tid] = x - v0;
    if (tid + 32 < nb) bsum[tid + 32] = total0 + y - v1;
}
__global__ void scan3_kernel(const int* __restrict__ cnt, const int* __restrict__ bsum,
                             int* __restrict__ off, int* __restrict__ fill, int Ntot, int N) {
    __shared__ int ws[32];
    int i = blockIdx.x * 1024 + threadIdx.x;
    int tid = threadIdx.x;
    int v = (i < Ntot) ? cnt[i] : 0;
    int x = v;
    #pragma unroll
    for (int d = 1; d < 32; d <<= 1) {
        int t = __shfl_up_sync(0xffffffffu, x, d);
        if ((tid & 31) >= d) x += t;
    }
    if ((tid & 31) == 31) ws[tid >> 5] = x;
    __syncthreads();
    if (tid < 32) {
        int w = ws[tid];
        #pragma unroll
        for (int d = 1; d < 32; d <<= 1) {
            int t = __shfl_up_sync(0xffffffffu, w, d);
            if (tid >= d) w += t;
        }
        ws[tid] = w;
    }
    __syncthreads();
    int warpOff = (tid >= 32) ? ws[(tid >> 5) - 1] : 0;
    int excl = bsum[blockIdx.x] + warpOff + x - v;
    if (i < Ntot) {
        off[i] = excl;
        if (i < N) fill[i] = excl;
    }
}
__global__ void fill_kernel(const int* __restrict__ src, const int* __restrict__ dst,
                            int* __restrict__ fill, int* __restrict__ srcs, int E) {
    int e = blockIdx.x * blockDim.x + threadIdx.x;
    if (e < E) {
        int p = atomicAdd(&fill[dst[e]], 1);
        srcs[p] = src[e];
    }
}

// ---------------- GEMM: K=128 bf16, 64-k chunks, partial in/out, fused pool ----------------
#define APAD 72
#define STG_ELEMS (2 * 128 * APAD)
#define POOL_SPAN 4
#define SMEM_GEMM (2 * STG_ELEMS * 2 + 1024 + POOL_SPAN * 128 * 4)

__device__ __forceinline__ void stage_chunk(
    const __nv_bfloat16* __restrict__ A, const __nv_bfloat16* __restrict__ wt,
    unsigned sbase, int kg, int rowBase, int M, int tid)
{
    #pragma unroll
    for (int p = 0; p < 4; ++p) {
        int idx = p * 256 + tid;
        int row = idx >> 3, seg = idx & 7;
        int g = rowBase + row;
        int pb = (g < M) ? 16 : 0;
        int gc = (g < M) ? g : 0;
        cpa16(sbase + (row * APAD + seg * 8) * 2,
              A + (size_t)gc * 128 + kg + seg * 8, pb);
    }
    #pragma unroll
    for (int p = 0; p < 4; ++p) {
        int idx = p * 256 + tid;
        int n = idx >> 3, seg = idx & 7;
        cpa16(sbase + (128 * APAD + n * APAD + seg * 8) * 2,
              wt + (size_t)n * 128 + kg + seg * 8, 16);
    }
}

__global__ __launch_bounds__(256, 2)
void gemm_mma(const __nv_bfloat16* __restrict__ A, const __nv_bfloat16* __restrict__ wt,
              const float* __restrict__ bias,
              __nv_bfloat16* __restrict__ C,
              const float* __restrict__ partIn, float* __restrict__ partOut,
              const int* __restrict__ batch, float* __restrict__ pooled,
              int M, int doNorm)
{
    extern __shared__ __align__(16) __nv_bfloat16 smem[];
    float* rowss = (float*)(smem + 2 * STG_ELEMS);
    float* spool = rowss + 256;
    const unsigned sb = (unsigned)__cvta_generic_to_shared(smem);

    const int tid = threadIdx.x;
    const int wid = tid >> 5, lane = tid & 31;
    const int wm = wid & 3, wn = wid >> 2;
    const int g4 = lane >> 2, q = lane & 3;
    const int rowBase = blockIdx.x * 128;

    const int aRow = wm * 32 + (lane & 15);
    const int aCol = (lane & 16) ? 8 : 0;
    const unsigned aAddr0 = sb + (unsigned)(aRow * APAD + aCol) * 2;
    const int bRow = wn * 64 + (lane & 7) + ((lane & 16) ? 8 : 0);
    const int bCol = (lane & 8) ? 8 : 0;
    const unsigned bAddr0 = sb + (unsigned)(128 * APAD + bRow * APAD + bCol) * 2;
    const unsigned I16 = 16 * APAD * 2;

    float acc[2][8][4];
    #pragma unroll
    for (int i = 0; i < 2; ++i)
        #pragma unroll
        for (int j = 0; j < 8; ++j)
            #pragma unroll
            for (int v = 0; v < 4; ++v) acc[i][j][v] = 0.0f;

    stage_chunk(A, wt, sb, 0, rowBase, M, tid);
    cpa_commit();

    #pragma unroll
    for (int kc = 0; kc < 2; ++kc) {
        cpa_wait0();
        __syncthreads();
        if (kc == 0) {
            stage_chunk(A, wt, sb + STG_ELEMS * 2, 64, rowBase, M, tid);
            cpa_commit();
        }
        const unsigned stoff = ((unsigned)(kc & 1)) * STG_ELEMS * 2;
        #pragma unroll
        for (int k16 = 0; k16 < 4; ++k16) {
            const unsigned kb = (unsigned)k16 * 32;
            unsigned a0[4], a1[4];
            ldsm_x4(a0, aAddr0 + stoff + kb);
            ldsm_x4(a1, aAddr0 + stoff + kb + I16);
            unsigned bh[4][4];
            #pragma unroll
            for (int jj = 0; jj < 4; ++jj)
                ldsm_x4(bh[jj], bAddr0 + stoff + kb + (unsigned)jj * I16);
            #pragma unroll
            for (int jj = 0; jj < 4; ++jj) {
                mma16816(acc[0][2 * jj],     a0, &bh[jj][0]);
                mma16816(acc[1][2 * jj],     a1, &bh[jj][0]);
                mma16816(acc[0][2 * jj + 1], a0, &bh[jj][2]);
                mma16816(acc[1][2 * jj + 1], a1, &bh[jj][2]);
            }
        }
    }

    // ---- partial-out mode: raw acc -> fp32, done ----
    if (partOut) {
        #pragma unroll
        for (int i = 0; i < 2; ++i) {
            int r0 = rowBase + wm * 32 + i * 16 + g4;
            #pragma unroll
            for (int j = 0; j < 8; ++j) {
                int col = wn * 64 + j * 8 + q * 2;
                if (r0 < M)
                    *(float2*)(partOut + (size_t)r0 * 128 + col) = make_float2(acc[i][j][0], acc[i][j][1]);
                if (r0 + 8 < M)
                    *(float2*)(partOut + (size_t)(r0 + 8) * 128 + col) = make_float2(acc[i][j][2], acc[i][j][3]);
            }
        }
        return;
    }

    // ---- partial-in: add fp32 partial ----
    if (partIn) {
        #pragma unroll
        for (int i = 0; i < 2; ++i) {
            int r0 = rowBase + wm * 32 + i * 16 + g4;
            #pragma unroll
            for (int j = 0; j < 8; ++j) {
                int col = wn * 64 + j * 8 + q * 2;
                if (r0 < M) {
                    float2 pv = *(const float2*)(partIn + (size_t)r0 * 128 + col);
                    acc[i][j][0] += pv.x; acc[i][j][1] += pv.y;
                }
                if (r0 + 8 < M) {
                    float2 pv = *(const float2*)(partIn + (size_t)(r0 + 8) * 128 + col);
                    acc[i][j][2] += pv.x; acc[i][j][3] += pv.y;
                }
            }
        }
    }

    // ---- bias + relu (+ norm) ----
    #pragma unroll
    for (int j = 0; j < 8; ++j) {
        int col = wn * 64 + j * 8 + q * 2;
        float2 b = *(const float2*)(bias + col);
        #pragma unroll
        for (int i = 0; i < 2; ++i) {
            acc[i][j][0] = fmaxf(acc[i][j][0] + b.x, 0.0f);
            acc[i][j][1] = fmaxf(acc[i][j][1] + b.y, 0.0f);
            acc[i][j][2] = fmaxf(acc[i][j][2] + b.x, 0.0f);
            acc[i][j][3] = fmaxf(acc[i][j][3] + b.y, 0.0f);
        }
    }
    if (doNorm) {
        __syncthreads();
        #pragma unroll
        for (int i = 0; i < 2; ++i) {
            int r = wm * 32 + i * 16 + g4;
            float ssLo = 0.f, ssHi = 0.f;
            #pragma unroll
            for (int j = 0; j < 8; ++j) {
                ssLo += acc[i][j][0] * acc[i][j][0] + acc[i][j][1] * acc[i][j][1];
                ssHi += acc[i][j][2] * acc[i][j][2] + acc[i][j][3] * acc[i][j][3];
            }
            ssLo += __shfl_xor_sync(0xffffffffu, ssLo, 1);
            ssLo += __shfl_xor_sync(0xffffffffu, ssLo, 2);
            ssHi += __shfl_xor_sync(0xffffffffu, ssHi, 1);
            ssHi += __shfl_xor_sync(0xffffffffu, ssHi, 2);
            if (q == 0) { rowss[r * 2 + wn] = ssLo; rowss[(r + 8) * 2 + wn] = ssHi; }
        }
        __syncthreads();
        #pragma unroll
        for (int i = 0; i < 2; ++i) {
            int r = wm * 32 + i * 16 + g4;
            float invLo = 1.0f / fmaxf(sqrtf(rowss[r * 2] + rowss[r * 2 + 1]), 1e-12f);
            float invHi = 1.0f / fmaxf(sqrtf(rowss[(r + 8) * 2] + rowss[(r + 8) * 2 + 1]), 1e-12f);
            #pragma unroll
            for (int j = 0; j < 8; ++j) {
                acc[i][j][0] *= invLo; acc[i][j][1] *= invLo;
                acc[i][j][2] *= invHi; acc[i][j][3] *= invHi;
            }
        }
    }

    if (pooled) {
        for (int s = tid; s < POOL_SPAN * 128; s += 256) spool[s] = 0.0f;
        __syncthreads();
        const int gLo = batch[rowBase];
        #pragma unroll
        for (int i = 0; i < 2; ++i) {
            int r0 = rowBase + wm * 32 + i * 16 + g4;
            int r1 = r0 + 8;
            int dg0 = (r0 < M) ? (batch[r0] - gLo) : -1;
            int dg1 = (r1 < M) ? (batch[r1] - gLo) : -1;
            #pragma unroll
            for (int j = 0; j < 8; ++j) {
                int col = wn * 64 + j * 8 + q * 2;
                if (dg0 >= 0) {
                    if (dg0 < POOL_SPAN) {
                        atomicMax((int*)&spool[dg0 * 128 + col],     __float_as_int(acc[i][j][0]));
                        atomicMax((int*)&spool[dg0 * 128 + col + 1], __float_as_int(acc[i][j][1]));
                    } else {
                        atomicMax((int*)&pooled[(gLo + dg0) * 128 + col],     __float_as_int(acc[i][j][0]));
                        atomicMax((int*)&pooled[(gLo + dg0) * 128 + col + 1], __float_as_int(acc[i][j][1]));
                    }
                }
                if (dg1 >= 0) {
                    if (dg1 < POOL_SPAN) {
                        atomicMax((int*)&spool[dg1 * 128 + col],     __float_as_int(acc[i][j][2]));
                        atomicMax((int*)&spool[dg1 * 128 + col + 1], __float_as_int(acc[i][j][3]));
                    } else {
                        atomicMax((int*)&pooled[(gLo + dg1) * 128 + col],     __float_as_int(acc[i][j][2]));
                        atomicMax((int*)&pooled[(gLo + dg1) * 128 + col + 1], __float_as_int(acc[i][j][3]));
                    }
                }
            }
        }
        __syncthreads();
        for (int s = tid; s < POOL_SPAN * 128; s += 256) {
            float v = spool[s];
            int gIdx = gLo + (s >> 7);
            if (v > 0.0f && gIdx < NGRAPH)
                atomicMax((int*)&pooled[gIdx * 128 + (s & 127)], __float_as_int(v));
        }
    } else {
        #pragma unroll
        for (int i = 0; i < 2; ++i) {
            int r0 = rowBase + wm * 32 + i * 16 + g4;
            #pragma unroll
            for (int j = 0; j < 8; ++j) {
                int col = wn * 64 + j * 8 + q * 2;
                __nv_bfloat162 p0(__float2bfloat16(acc[i][j][0]), __float2bfloat16(acc[i][j][1]));
                __nv_bfloat162 p1(__float2bfloat16(acc[i][j][2]), __float2bfloat16(acc[i][j][3]));
                if (r0 < M)
                    *(__nv_bfloat162*)(C + (size_t)r0 * 128 + col) = p0;
                if (r0 + 8 < M)
                    *(__nv_bfloat162*)(C + (size_t)(r0 + 8) * 128 + col) = p1;
            }
        }
    }
}

// ---------------- CSR mean aggregation ----------------
__global__ void agg_kernel(const __nv_bfloat16* __restrict__ y,
                           __nv_bfloat16* __restrict__ agg,
                           const int* __restrict__ off, const int* __restrict__ srcs,
                           int N)
{
    int w = (blockIdx.x * blockDim.x + threadIdx.x) >> 5;
    int lane = threadIdx.x & 31;
    if (w >= N) return;
    int s0 = off[w], s1 = off[w + 1];
    float acc0 = 0.f, acc1 = 0.f, acc2 = 0.f, acc3 = 0.f;
    int i = s0;
    for (; i + 1 < s1; i += 2) {
        int sA = __ldg(&srcs[i]);
        int sB = __ldg(&srcs[i + 1]);
        uint2 hA = *(const uint2*)(y + (size_t)sA * 128 + lane * 4);
        uint2 hB = *(const uint2*)(y + (size_t)sB * 128 + lane * 4);
        float2 a = __bfloat1622float2(*(const __nv_bfloat162*)&hA.x);
        float2 b = __bfloat1622float2(*(const __nv_bfloat162*)&hA.y);
        acc0 += a.x; acc1 += a.y; acc2 += b.x; acc3 += b.y;
        a = __bfloat1622float2(*(const __nv_bfloat162*)&hB.x);
        b = __bfloat1622float2(*(const __nv_bfloat162*)&hB.y);
        acc0 += a.x; acc1 += a.y; acc2 += b.x; acc3 += b.y;
    }
    if (i < s1) {
        int sA = __ldg(&srcs[i]);
        uint2 hA = *(const uint2*)(y + (size_t)sA * 128 + lane * 4);
        float2 a = __bfloat1622float2(*(const __nv_bfloat162*)&hA.x);
        float2 b = __bfloat1622float2(*(const __nv_bfloat162*)&hA.y);
        acc0 += a.x; acc1 += a.y; acc2 += b.x; acc3 += b.y;
    }
    float inv = 1.0f / fmaxf((float)(s1 - s0), 1.0f);
    __nv_bfloat162 p0(__float2bfloat16(acc0 * inv), __float2bfloat16(acc1 * inv));
    __nv_bfloat162 p1(__float2bfloat16(acc2 * inv), __float2bfloat16(acc3 * inv));
    *(__nv_bfloat162*)(agg + (size_t)w * 128 + lane * 4)     = p0;
    *(__nv_bfloat162*)(agg + (size_t)w * 128 + lane * 4 + 2) = p1;
}

// ---------------- head ----------------
__global__ void head_kernel(const float* __restrict__ pooled,
                            const float* __restrict__ w1, const float* __restrict__ b1,
                            const float* __restrict__ w2, const float* __restrict__ b2,
                            float* __restrict__ out)
{
    __shared__ float t[NGRAPH][HID];
    int tid = threadIdx.x;
    for (int o = tid; o < NGRAPH * HID; o += blockDim.x) {
        int r = o >> 7, c = o & 127;
        float s = b1[c];
        #pragma unroll 8
        for (int k = 0; k < 128; ++k) s = fmaf(pooled[r * 128 + k], w1[k * 128 + c], s);
        t[r][c] = s;
    }
    __syncthreads();
    if (tid < NGRAPH) {
        float z0 = b2[0], z1 = b2[1];
        #pragma unroll 8
        for (int k = 0; k < 128; ++k) {
            float v = t[tid][k];
            z0 = fmaf(v, w2[k * 2 + 0], z0);
            z1 = fmaf(v, w2[k * 2 + 1], z1);
        }
        float m = fmaxf(z0, z1);
        float lse = m + logf(expf(z0 - m) + expf(z1 - m));
        out[tid * 2 + 0] = z0 - lse;
        out[tid * 2 + 1] = z1 - lse;
    }
}

// ---------------- launch ----------------
static cudaStream_t g_s2 = nullptr, g_s3 = nullptr;
static cudaEvent_t  g_e1 = nullptr, g_e2 = nullptr, g_eX = nullptr,
                    g_eP0 = nullptr, g_eH = nullptr, g_eP1 = nullptr;

extern "C" void kernel_launch(void* const* d_in, const int* in_sizes, int n_in,
                              void* d_out, int out_size)
{
    const float* x      = (const float*)d_in[0];
    const int*   ei     = (const int*)  d_in[1];
    const int*   batch  = (const int*)  d_in[2];
    const float* lin_w0 = (const float*)d_in[3];
    const float* lin_b0 = (const float*)d_in[4];
    const float* agg_w0 = (const float*)d_in[5];
    const float* agg_b0 = (const float*)d_in[6];
    const float* lin_w1 = (const float*)d_in[7];
    const float* lin_b1 = (const float*)d_in[8];
    const float* agg_w1 = (const float*)d_in[9];
    const float* agg_b1 = (const float*)d_in[10];
    const float* mp_w1  = (const float*)d_in[11];
    const float* mp_b1  = (const float*)d_in[12];
    const float* mp_w2  = (const float*)d_in[13];
    const float* mp_b2  = (const float*)d_in[14];
    float* out = (float*)d_out;

    const int N = in_sizes[0] / HID;
    const int E = in_sizes[1] / 2;
    const int* src = ei;
    const int* dst = ei + E;

    if (!g_s2) {
        cudaStreamCreateWithFlags(&g_s2, cudaStreamNonBlocking);
        cudaStreamCreateWithFlags(&g_s3, cudaStreamNonBlocking);
        cudaEventCreateWithFlags(&g_e1, cudaEventDisableTiming);
        cudaEventCreateWithFlags(&g_e2, cudaEventDisableTiming);
        cudaEventCreateWithFlags(&g_eX, cudaEventDisableTiming);
        cudaEventCreateWithFlags(&g_eP0, cudaEventDisableTiming);
        cudaEventCreateWithFlags(&g_eH, cudaEventDisableTiming);
        cudaEventCreateWithFlags(&g_eP1, cudaEventDisableTiming);
    }

    void *p;
    float *pooled, *part;
    int *cnt, *off, *fill, *srcs, *bsum;
    __nv_bfloat16 *xb, *yb, *h0b, *aggb, *wt;
    cudaGetSymbolAddress(&p, g_pooled); pooled = (float*)p;
    cudaGetSymbolAddress(&p, g_part);   part   = (float*)p;
    cudaGetSymbolAddress(&p, g_cnt);    cnt    = (int*)p;
    cudaGetSymbolAddress(&p, g_off);    off    = (int*)p;
    cudaGetSymbolAddress(&p, g_fill);   fill   = (int*)p;
    cudaGetSymbolAddress(&p, g_srcs);   srcs   = (int*)p;
    cudaGetSymbolAddress(&p, g_bsum);   bsum   = (int*)p;
    cudaGetSymbolAddress(&p, g_xb);     xb     = (__nv_bfloat16*)p;
    cudaGetSymbolAddress(&p, g_yb);     yb     = (__nv_bfloat16*)p;
    cudaGetSymbolAddress(&p, g_h0b);    h0b    = (__nv_bfloat16*)p;
    cudaGetSymbolAddress(&p, g_aggb);   aggb   = (__nv_bfloat16*)p;
    cudaGetSymbolAddress(&p, g_wt);     wt     = (__nv_bfloat16*)p;

    cudaFuncSetAttribute(gemm_mma, cudaFuncAttributeMaxDynamicSharedMemorySize, SMEM_GEMM);

    const int nTiles = (N + 127) / 128;
    const int Ntot = N + 1;
    const int nScanB = (Ntot + 1023) / 1024;

    cudaEventRecord(g_e1, 0);     // fork for CSR stream

    // ---- s0: converts + lin0 ----
    {
        dim3 g((128 * 256 + 255) / 256, 4);
        wconvert_all<<<g, 256>>>(lin_w0, agg_w0, lin_w1, agg_w1, wt);
    }
    xconvert_kernel<<<(N * 32 + 255) / 256, 256>>>(x, xb, N * 32);
    cudaEventRecord(g_eX, 0);
    gemm_mma<<<nTiles, 256, SMEM_GEMM>>>(xb, wt, lin_b0, yb,
                                         nullptr, nullptr, nullptr, nullptr, N, 0);

    // ---- s3: partial0 = x @ Wx0 ----
    cudaStreamWaitEvent(g_s3, g_eX, 0);
    gemm_mma<<<nTiles, 256, SMEM_GEMM, g_s3>>>(xb, wt + 32768, nullptr, nullptr,
                                               nullptr, part, nullptr, nullptr, N, 0);
    cudaEventRecord(g_eP0, g_s3);

    // ---- s2: CSR build + zero pool ----
    cudaStreamWaitEvent(g_s2, g_e1, 0);
    zero_cnt_kernel<<<(Ntot + 255) / 256, 256, 0, g_s2>>>(cnt, Ntot);
    hist_kernel<<<(E + 255) / 256, 256, 0, g_s2>>>(dst, cnt, E);
    scan1_kernel<<<nScanB, 1024, 0, g_s2>>>(cnt, bsum, Ntot);
    scan2_kernel<<<1, 32, 0, g_s2>>>(bsum, nScanB);
    scan3_kernel<<<nScanB, 1024, 0, g_s2>>>(cnt, bsum, off, fill, Ntot, N);
    fill_kernel<<<(E + 255) / 256, 256, 0, g_s2>>>(src, dst, fill, srcs, E);
    zero_pool_kernel<<<(NGRAPH * HID + 255) / 256, 256, 0, g_s2>>>(pooled, NGRAPH * HID);
    cudaEventRecord(g_e2, g_s2);

    // ---- layer 0 ----
    cudaStreamWaitEvent(0, g_e2, 0);
    agg_kernel<<<(N + 7) / 8, 256>>>(yb, aggb, off, srcs, N);
    cudaStreamWaitEvent(0, g_eP0, 0);
    gemm_mma<<<nTiles, 256, SMEM_GEMM>>>(aggb, wt + 16384, agg_b0, h0b,
                                         part, nullptr, nullptr, nullptr, N, 1);
    cudaEventRecord(g_eH, 0);

    // ---- layer 1: lin1 (s0) || partial1 (s3) ----
    gemm_mma<<<nTiles, 256, SMEM_GEMM>>>(h0b, wt + 49152, lin_b1, yb,
                                         nullptr, nullptr, nullptr, nullptr, N, 0);
    cudaStreamWaitEvent(g_s3, g_eH, 0);
    gemm_mma<<<nTiles, 256, SMEM_GEMM, g_s3>>>(h0b, wt + 81920, nullptr, nullptr,
                                               nullptr, part, nullptr, nullptr, N, 0);
    cudaEventRecord(g_eP1, g_s3);

    agg_kernel<<<(N + 7) / 8, 256>>>(yb, aggb, off, srcs, N);
    cudaStreamWaitEvent(0, g_eP1, 0);
    gemm_mma<<<nTiles, 256, SMEM_GEMM>>>(aggb, wt + 65536, agg_b1, nullptr,
                                         part, nullptr, batch, pooled, N, 1);

    head_kernel<<<1, 256>>>(pooled, mp_w1, mp_b1, mp_w2, mp_b2, out);
}

// round 15
// speedup vs baseline: 1.0773x; 1.0773x over previous
#include <cuda_runtime.h>
#include <cuda_bf16.h>
#include <math.h>

#define MAXN 50000
#define MAXE 600000
#define HID 128
#define NGRAPH 64

// ---------------- scratch (static device globals) ----------------
__device__ __nv_bfloat16 g_xb[(size_t)MAXN * HID];
__device__ __nv_bfloat16 g_yb[(size_t)MAXN * HID];
__device__ __nv_bfloat16 g_h0b[(size_t)MAXN * HID];
__device__ __nv_bfloat16 g_aggb[(size_t)MAXN * HID];
__device__ int   g_cnt[MAXN + 1];
__device__ int   g_off[MAXN + 1];
__device__ int   g_fill[MAXN];
__device__ int   g_srcs[MAXE];
__device__ int   g_bsum[64];
__device__ float g_pooled[NGRAPH * HID];
__device__ __nv_bfloat16 g_wt[128 * 768];

// ---------------- tiny helpers ----------------
__device__ __forceinline__ void cpa16(unsigned dst, const void* src, int pbytes) {
    asm volatile("cp.async.cg.shared.global [%0], [%1], 16, %2;\n"
                 :: "r"(dst), "l"(src), "r"(pbytes));
}
__device__ __forceinline__ void cpa_commit() { asm volatile("cp.async.commit_group;\n"); }
__device__ __forceinline__ void cpa_wait0()  { asm volatile("cp.async.wait_group 0;\n"); }

__device__ __forceinline__ void mma16816(float c[4], const unsigned a[4], const unsigned* b) {
    asm volatile(
        "mma.sync.aligned.m16n8k16.row.col.f32.bf16.bf16.f32 "
        "{%0,%1,%2,%3},{%4,%5,%6,%7},{%8,%9},{%0,%1,%2,%3};"
        : "+f"(c[0]), "+f"(c[1]), "+f"(c[2]), "+f"(c[3])
        : "r"(a[0]), "r"(a[1]), "r"(a[2]), "r"(a[3]), "r"(b[0]), "r"(b[1]));
}
__device__ __forceinline__ void ldsm_x4(unsigned r[4], unsigned addr) {
    asm volatile("ldmatrix.sync.aligned.m8n8.x4.shared.b16 {%0,%1,%2,%3}, [%4];"
                 : "=r"(r[0]), "=r"(r[1]), "=r"(r[2]), "=r"(r[3]) : "r"(addr));
}

// ---------------- conversion kernels ----------------
__global__ void wconvert_all(const float* __restrict__ w0, const float* __restrict__ wa0,
                             const float* __restrict__ w1, const float* __restrict__ wa1,
                             __nv_bfloat16* __restrict__ wt)
{
    const int r = blockIdx.y;
    const int K   = (r & 1) ? 256 : 128;
    const int off = (r == 0) ? 0 : (r == 1) ? 16384 : (r == 2) ? 49152 : 65536;
    const float* W = (r == 0) ? w0 : (r == 1) ? wa0 : (r == 2) ? w1 : wa1;
    int idx = blockIdx.x * blockDim.x + threadIdx.x;
    if (idx >= 128 * K) return;
    int n = idx / K, k = idx % K;
    wt[off + idx] = __float2bfloat16(W[(size_t)k * 128 + n]);
}

__global__ void xconvert_kernel(const float* __restrict__ x,
                                __nv_bfloat16* __restrict__ xb, int total4)
{
    int i = blockIdx.x * blockDim.x + threadIdx.x;
    if (i >= total4) return;
    float4 v = *(const float4*)(x + (size_t)i * 4);
    __nv_bfloat162 p0(__float2bfloat16(v.x), __float2bfloat16(v.y));
    __nv_bfloat162 p1(__float2bfloat16(v.z), __float2bfloat16(v.w));
    *(__nv_bfloat162*)(xb + (size_t)i * 4)     = p0;
    *(__nv_bfloat162*)(xb + (size_t)i * 4 + 2) = p1;
}

// ---------------- CSR build ----------------
__global__ void zero_pool_kernel(float* pooled, int npool) {
    int i = blockIdx.x * blockDim.x + threadIdx.x;
    if (i < npool) pooled[i] = 0.0f;
}
__global__ void zero_cnt_kernel(int* cnt, int ncnt) {
    int i = blockIdx.x * blockDim.x + threadIdx.x;
    if (i < ncnt) cnt[i] = 0;
}
__global__ void hist_kernel(const int* __restrict__ dst, int* __restrict__ cnt, int E) {
    int e = blockIdx.x * blockDim.x + threadIdx.x;
    if (e < E) atomicAdd(&cnt[dst[e]], 1);
}
__global__ void scan1_kernel(const int* __restrict__ cnt, int* __restrict__ bsum, int Ntot) {
    __shared__ int ws[32];
    int i = blockIdx.x * 1024 + threadIdx.x;
    int v = (i < Ntot) ? cnt[i] : 0;
    #pragma unroll
    for (int d = 16; d > 0; d >>= 1) v += __shfl_down_sync(0xffffffffu, v, d);
    if ((threadIdx.x & 31) == 0) ws[threadIdx.x >> 5] = v;
    __syncthreads();
    if (threadIdx.x < 32) {
        int s = ws[threadIdx.x];
        #pragma unroll
        for (int d = 16; d > 0; d >>= 1) s += __shfl_down_sync(0xffffffffu, s, d);
        if (threadIdx.x == 0) bsum[blockIdx.x] = s;
    }
}
__global__ void scan2_kernel(int* __restrict__ bsum, int nb) {
    int tid = threadIdx.x;
    int v0 = (tid < nb) ? bsum[tid] : 0;
    int v1 = (tid + 32 < nb) ? bsum[tid + 32] : 0;
    int x = v0;
    #pragma unroll
    for (int d = 1; d < 32; d <<= 1) {
        int t = __shfl_up_sync(0xffffffffu, x, d);
        if (tid >= d) x += t;
    }
    int total0 = __shfl_sync(0xffffffffu, x, 31);
    int y = v1;
    #pragma unroll
    for (int d = 1; d < 32; d <<= 1) {
        int t = __shfl_up_sync(0xffffffffu, y, d);
        if (tid >= d) y += t;
    }
    if (tid < nb) bsum[tid] = x - v0;
    if (tid + 32 < nb) bsum[tid + 32] = total0 + y - v1;
}
__global__ void scan3_kernel(const int* __restrict__ cnt, const int* __restrict__ bsum,
                             int* __restrict__ off, int* __restrict__ fill, int Ntot, int N) {
    __shared__ int ws[32];
    int i = blockIdx.x * 1024 + threadIdx.x;
    int tid = threadIdx.x;
    int v = (i < Ntot) ? cnt[i] : 0;
    int x = v;
    #pragma unroll
    for (int d = 1; d < 32; d <<= 1) {
        int t = __shfl_up_sync(0xffffffffu, x, d);
        if ((tid & 31) >= d) x += t;
    }
    if ((tid & 31) == 31) ws[tid >> 5] = x;
    __syncthreads();
    if (tid < 32) {
        int w = ws[tid];
        #pragma unroll
        for (int d = 1; d < 32; d <<= 1) {
            int t = __shfl_up_sync(0xffffffffu, w, d);
            if (tid >= d) w += t;
        }
        ws[tid] = w;
    }
    __syncthreads();
    int warpOff = (tid >= 32) ? ws[(tid >> 5) - 1] : 0;
    int excl = bsum[blockIdx.x] + warpOff + x - v;
    if (i < Ntot) {
        off[i] = excl;
        if (i < N) fill[i] = excl;
    }
}
__global__ void fill_kernel(const int* __restrict__ src, const int* __restrict__ dst,
                            int* __restrict__ fill, int* __restrict__ srcs, int E) {
    int e = blockIdx.x * blockDim.x + threadIdx.x;
    if (e < E) {
        int p = atomicAdd(&fill[dst[e]], 1);
        srcs[p] = src[e];
    }
}

// ---------------- GEMM: single-pass bf16, 64-k chunks, 2-stage cp.async, fused pool --------
#define APAD 72
#define STG_ELEMS (2 * 128 * APAD)
#define POOL_SPAN 4
#define SMEM_GEMM (2 * STG_ELEMS * 2 + 1024 + POOL_SPAN * 128 * 4)

__device__ __forceinline__ void stage_chunk(
    const __nv_bfloat16* __restrict__ A1, const __nv_bfloat16* __restrict__ A2,
    const __nv_bfloat16* __restrict__ wt,
    int Ktot, unsigned sbase, int kg, int rowBase, int M, int tid)
{
    const __nv_bfloat16* A = (kg < 128) ? A1 : A2;
    const int kk = (kg < 128) ? kg : kg - 128;
    #pragma unroll
    for (int p = 0; p < 4; ++p) {
        int idx = p * 256 + tid;
        int row = idx >> 3, seg = idx & 7;
        int g = rowBase + row;
        int pb = (g < M) ? 16 : 0;
        int gc = (g < M) ? g : 0;
        cpa16(sbase + (row * APAD + seg * 8) * 2,
              A + (size_t)gc * 128 + kk + seg * 8, pb);
    }
    #pragma unroll
    for (int p = 0; p < 4; ++p) {
        int idx = p * 256 + tid;
        int n = idx >> 3, seg = idx & 7;
        cpa16(sbase + (128 * APAD + n * APAD + seg * 8) * 2,
              wt + (size_t)n * Ktot + kg + seg * 8, 16);
    }
}

__global__ __launch_bounds__(256, 2)
void gemm_mma(const __nv_bfloat16* __restrict__ A1, const __nv_bfloat16* __restrict__ A2,
              const __nv_bfloat16* __restrict__ wt,
              int Ktot, const float* __restrict__ bias,
              __nv_bfloat16* __restrict__ C,
              const int* __restrict__ batch, float* __restrict__ pooled,
              int M, int doNorm)
{
    extern __shared__ __align__(16) __nv_bfloat16 smem[];
    float* rowss = (float*)(smem + 2 * STG_ELEMS);
    float* spool = rowss + 256;
    const unsigned sb = (unsigned)__cvta_generic_to_shared(smem);

    const int tid = threadIdx.x;
    const int wid = tid >> 5, lane = tid & 31;
    const int wm = wid & 3, wn = wid >> 2;
    const int g4 = lane >> 2, q = lane & 3;
    const int rowBase = blockIdx.x * 128;

    const int aRow = wm * 32 + (lane & 15);
    const int aCol = (lane & 16) ? 8 : 0;
    const unsigned aAddr0 = sb + (unsigned)(aRow * APAD + aCol) * 2;
    const int bRow = wn * 64 + (lane & 7) + ((lane & 16) ? 8 : 0);
    const int bCol = (lane & 8) ? 8 : 0;
    const unsigned bAddr0 = sb + (unsigned)(128 * APAD + bRow * APAD + bCol) * 2;
    const unsigned I16 = 16 * APAD * 2;
    const int nChunks = Ktot / 64;

    float acc[2][8][4];
    #pragma unroll
    for (int i = 0; i < 2; ++i)
        #pragma unroll
        for (int j = 0; j < 8; ++j)
            #pragma unroll
            for (int v = 0; v < 4; ++v) acc[i][j][v] = 0.0f;

    stage_chunk(A1, A2, wt, Ktot, sb, 0, rowBase, M, tid);
    cpa_commit();

    for (int kc = 0; kc < nChunks; ++kc) {
        cpa_wait0();
        __syncthreads();
        if (kc + 1 < nChunks) {
            stage_chunk(A1, A2, wt, Ktot,
                        sb + ((kc + 1) & 1) * STG_ELEMS * 2, (kc + 1) * 64, rowBase, M, tid);
            cpa_commit();
        }
        const unsigned stoff = ((unsigned)(kc & 1)) * STG_ELEMS * 2;
        #pragma unroll
        for (int k16 = 0; k16 < 4; ++k16) {
            const unsigned kb = (unsigned)k16 * 32;
            unsigned a0[4], a1[4];
            ldsm_x4(a0, aAddr0 + stoff + kb);
            ldsm_x4(a1, aAddr0 + stoff + kb + I16);
            unsigned bh[4][4];
            #pragma unroll
            for (int jj = 0; jj < 4; ++jj)
                ldsm_x4(bh[jj], bAddr0 + stoff + kb + (unsigned)jj * I16);
            #pragma unroll
            for (int jj = 0; jj < 4; ++jj) {
                mma16816(acc[0][2 * jj],     a0, &bh[jj][0]);
                mma16816(acc[1][2 * jj],     a1, &bh[jj][0]);
                mma16816(acc[0][2 * jj + 1], a0, &bh[jj][2]);
                mma16816(acc[1][2 * jj + 1], a1, &bh[jj][2]);
            }
        }
    }

    #pragma unroll
    for (int j = 0; j < 8; ++j) {
        int col = wn * 64 + j * 8 + q * 2;
        float2 b = *(const float2*)(bias + col);
        #pragma unroll
        for (int i = 0; i < 2; ++i) {
            acc[i][j][0] = fmaxf(acc[i][j][0] + b.x, 0.0f);
            acc[i][j][1] = fmaxf(acc[i][j][1] + b.y, 0.0f);
            acc[i][j][2] = fmaxf(acc[i][j][2] + b.x, 0.0f);
            acc[i][j][3] = fmaxf(acc[i][j][3] + b.y, 0.0f);
        }
    }
    if (doNorm) {
        __syncthreads();
        #pragma unroll
        for (int i = 0; i < 2; ++i) {
            int r = wm * 32 + i * 16 + g4;
            float ssLo = 0.f, ssHi = 0.f;
            #pragma unroll
            for (int j = 0; j < 8; ++j) {
                ssLo += acc[i][j][0] * acc[i][j][0] + acc[i][j][1] * acc[i][j][1];
                ssHi += acc[i][j][2] * acc[i][j][2] + acc[i][j][3] * acc[i][j][3];
            }
            ssLo += __shfl_xor_sync(0xffffffffu, ssLo, 1);
            ssLo += __shfl_xor_sync(0xffffffffu, ssLo, 2);
            ssHi += __shfl_xor_sync(0xffffffffu, ssHi, 1);
            ssHi += __shfl_xor_sync(0xffffffffu, ssHi, 2);
            if (q == 0) { rowss[r * 2 + wn] = ssLo; rowss[(r + 8) * 2 + wn] = ssHi; }
        }
        __syncthreads();
        #pragma unroll
        for (int i = 0; i < 2; ++i) {
            int r = wm * 32 + i * 16 + g4;
            float invLo = 1.0f / fmaxf(sqrtf(rowss[r * 2] + rowss[r * 2 + 1]), 1e-12f);
            float invHi = 1.0f / fmaxf(sqrtf(rowss[(r + 8) * 2] + rowss[(r + 8) * 2 + 1]), 1e-12f);
            #pragma unroll
            for (int j = 0; j < 8; ++j) {
                acc[i][j][0] *= invLo; acc[i][j][1] *= invLo;
                acc[i][j][2] *= invHi; acc[i][j][3] *= invHi;
            }
        }
    }

    if (pooled) {
        for (int s = tid; s < POOL_SPAN * 128; s += 256) spool[s] = 0.0f;
        __syncthreads();
        const int gLo = batch[rowBase];
        #pragma unroll
        for (int i = 0; i < 2; ++i) {
            int r0 = rowBase + wm * 32 + i * 16 + g4;
            int r1 = r0 + 8;
            int dg0 = (r0 < M) ? (batch[r0] - gLo) : -1;
            int dg1 = (r1 < M) ? (batch[r1] - gLo) : -1;
            #pragma unroll
            for (int j = 0; j < 8; ++j) {
                int col = wn * 64 + j * 8 + q * 2;
                if (dg0 >= 0) {
                    if (dg0 < POOL_SPAN) {
                        atomicMax((int*)&spool[dg0 * 128 + col],     __float_as_int(acc[i][j][0]));
                        atomicMax((int*)&spool[dg0 * 128 + col + 1], __float_as_int(acc[i][j][1]));
                    } else {
                        atomicMax((int*)&pooled[(gLo + dg0) * 128 + col],     __float_as_int(acc[i][j][0]));
                        atomicMax((int*)&pooled[(gLo + dg0) * 128 + col + 1], __float_as_int(acc[i][j][1]));
                    }
                }
                if (dg1 >= 0) {
                    if (dg1 < POOL_SPAN) {
                        atomicMax((int*)&spool[dg1 * 128 + col],     __float_as_int(acc[i][j][2]));
                        atomicMax((int*)&spool[dg1 * 128 + col + 1], __float_as_int(acc[i][j][3]));
                    } else {
                        atomicMax((int*)&pooled[(gLo + dg1) * 128 + col],     __float_as_int(acc[i][j][2]));
                        atomicMax((int*)&pooled[(gLo + dg1) * 128 + col + 1], __float_as_int(acc[i][j][3]));
                    }
                }
            }
        }
        __syncthreads();
        for (int s = tid; s < POOL_SPAN * 128; s += 256) {
            float v = spool[s];
            int gIdx = gLo + (s >> 7);
            if (v > 0.0f && gIdx < NGRAPH)
                atomicMax((int*)&pooled[gIdx * 128 + (s & 127)], __float_as_int(v));
        }
    } else {
        #pragma unroll
        for (int i = 0; i < 2; ++i) {
            int r0 = rowBase + wm * 32 + i * 16 + g4;
            #pragma unroll
            for (int j = 0; j < 8; ++j) {
                int col = wn * 64 + j * 8 + q * 2;
                __nv_bfloat162 p0(__float2bfloat16(acc[i][j][0]), __float2bfloat16(acc[i][j][1]));
                __nv_bfloat162 p1(__float2bfloat16(acc[i][j][2]), __float2bfloat16(acc[i][j][3]));
                if (r0 < M)
                    *(__nv_bfloat162*)(C + (size_t)r0 * 128 + col) = p0;
                if (r0 + 8 < M)
                    *(__nv_bfloat162*)(C + (size_t)(r0 + 8) * 128 + col) = p1;
            }
        }
    }
}

// ---------------- CSR mean aggregation: 4-way unrolled gather (MLP=4) ----------------
__global__ void agg_kernel(const __nv_bfloat16* __restrict__ y,
                           __nv_bfloat16* __restrict__ agg,
                           const int* __restrict__ off, const int* __restrict__ srcs,
                           int N)
{
    int w = (blockIdx.x * blockDim.x + threadIdx.x) >> 5;
    int lane = threadIdx.x & 31;
    if (w >= N) return;
    int s0 = off[w], s1 = off[w + 1];
    float acc0 = 0.f, acc1 = 0.f, acc2 = 0.f, acc3 = 0.f;
    int i = s0;
    for (; i + 3 < s1; i += 4) {
        int sA = __ldg(&srcs[i]);
        int sB = __ldg(&srcs[i + 1]);
        int sC = __ldg(&srcs[i + 2]);
        int sD = __ldg(&srcs[i + 3]);
        uint2 hA = *(const uint2*)(y + (size_t)sA * 128 + lane * 4);
        uint2 hB = *(const uint2*)(y + (size_t)sB * 128 + lane * 4);
        uint2 hC = *(const uint2*)(y + (size_t)sC * 128 + lane * 4);
        uint2 hD = *(const uint2*)(y + (size_t)sD * 128 + lane * 4);
        float2 a, b;
        a = __bfloat1622float2(*(const __nv_bfloat162*)&hA.x);
        b = __bfloat1622float2(*(const __nv_bfloat162*)&hA.y);
        acc0 += a.x; acc1 += a.y; acc2 += b.x; acc3 += b.y;
        a = __bfloat1622float2(*(const __nv_bfloat162*)&hB.x);
        b = __bfloat1622float2(*(const __nv_bfloat162*)&hB.y);
        acc0 += a.x; acc1 += a.y; acc2 += b.x; acc3 += b.y;
        a = __bfloat1622float2(*(const __nv_bfloat162*)&hC.x);
        b = __bfloat1622float2(*(const __nv_bfloat162*)&hC.y);
        acc0 += a.x; acc1 += a.y; acc2 += b.x; acc3 += b.y;
        a = __bfloat1622float2(*(const __nv_bfloat162*)&hD.x);
        b = __bfloat1622float2(*(const __nv_bfloat162*)&hD.y);
        acc0 += a.x; acc1 += a.y; acc2 += b.x; acc3 += b.y;
    }
    for (; i < s1; ++i) {
        int sA = __ldg(&srcs[i]);
        uint2 hA = *(const uint2*)(y + (size_t)sA * 128 + lane * 4);
        float2 a = __bfloat1622float2(*(const __nv_bfloat162*)&hA.x);
        float2 b = __bfloat1622float2(*(const __nv_bfloat162*)&hA.y);
        acc0 += a.x; acc1 += a.y; acc2 += b.x; acc3 += b.y;
    }
    float inv = 1.0f / fmaxf((float)(s1 - s0), 1.0f);
    __nv_bfloat162 p0(__float2bfloat16(acc0 * inv), __float2bfloat16(acc1 * inv));
    __nv_bfloat162 p1(__float2bfloat16(acc2 * inv), __float2bfloat16(acc3 * inv));
    *(__nv_bfloat162*)(agg + (size_t)w * 128 + lane * 4)     = p0;
    *(__nv_bfloat162*)(agg + (size_t)w * 128 + lane * 4 + 2) = p1;
}

// ---------------- head ----------------
__global__ void head_kernel(const float* __restrict__ pooled,
                            const float* __restrict__ w1, const float* __restrict__ b1,
                            const float* __restrict__ w2, const float* __restrict__ b2,
                            float* __restrict__ out)
{
    __shared__ float t[NGRAPH][HID];
    int tid = threadIdx.x;
    for (int o = tid; o < NGRAPH * HID; o += blockDim.x) {
        int r = o >> 7, c = o & 127;
        float s = b1[c];
        #pragma unroll 8
        for (int k = 0; k < 128; ++k) s = fmaf(pooled[r * 128 + k], w1[k * 128 + c], s);
        t[r][c] = s;
    }
    __syncthreads();
    if (tid < NGRAPH) {
        float z0 = b2[0], z1 = b2[1];
        #pragma unroll 8
        for (int k = 0; k < 128; ++k) {
            float v = t[tid][k];
            z0 = fmaf(v, w2[k * 2 + 0], z0);
            z1 = fmaf(v, w2[k * 2 + 1], z1);
        }
        float m = fmaxf(z0, z1);
        float lse = m + logf(expf(z0 - m) + expf(z1 - m));
        out[tid * 2 + 0] = z0 - lse;
        out[tid * 2 + 1] = z1 - lse;
    }
}

// ---------------- launch ----------------
static cudaStream_t g_s2 = nullptr;
static cudaEvent_t  g_e1 = nullptr, g_e2 = nullptr;

extern "C" void kernel_launch(void* const* d_in, const int* in_sizes, int n_in,
                              void* d_out, int out_size)
{
    const float* x      = (const float*)d_in[0];
    const int*   ei     = (const int*)  d_in[1];
    const int*   batch  = (const int*)  d_in[2];
    const float* lin_w0 = (const float*)d_in[3];
    const float* lin_b0 = (const float*)d_in[4];
    const float* agg_w0 = (const float*)d_in[5];
    const float* agg_b0 = (const float*)d_in[6];
    const float* lin_w1 = (const float*)d_in[7];
    const float* lin_b1 = (const float*)d_in[8];
    const float* agg_w1 = (const float*)d_in[9];
    const float* agg_b1 = (const float*)d_in[10];
    const float* mp_w1  = (const float*)d_in[11];
    const float* mp_b1  = (const float*)d_in[12];
    const float* mp_w2  = (const float*)d_in[13];
    const float* mp_b2  = (const float*)d_in[14];
    float* out = (float*)d_out;

    const int N = in_sizes[0] / HID;
    const int E = in_sizes[1] / 2;
    const int* src = ei;
    const int* dst = ei + E;

    if (!g_s2) {
        cudaStreamCreateWithFlags(&g_s2, cudaStreamNonBlocking);
        cudaEventCreateWithFlags(&g_e1, cudaEventDisableTiming);
        cudaEventCreateWithFlags(&g_e2, cudaEventDisableTiming);
    }

    void *p;
    float *pooled;
    int *cnt, *off, *fill, *srcs, *bsum;
    __nv_bfloat16 *xb, *yb, *h0b, *aggb, *wt;
    cudaGetSymbolAddress(&p, g_pooled); pooled = (float*)p;
    cudaGetSymbolAddress(&p, g_cnt);    cnt    = (int*)p;
    cudaGetSymbolAddress(&p, g_off);    off    = (int*)p;
    cudaGetSymbolAddress(&p, g_fill);   fill   = (int*)p;
    cudaGetSymbolAddress(&p, g_srcs);   srcs   = (int*)p;
    cudaGetSymbolAddress(&p, g_bsum);   bsum   = (int*)p;
    cudaGetSymbolAddress(&p, g_xb);     xb     = (__nv_bfloat16*)p;
    cudaGetSymbolAddress(&p, g_yb);     yb     = (__nv_bfloat16*)p;
    cudaGetSymbolAddress(&p, g_h0b);    h0b    = (__nv_bfloat16*)p;
    cudaGetSymbolAddress(&p, g_aggb);   aggb   = (__nv_bfloat16*)p;
    cudaGetSymbolAddress(&p, g_wt);     wt     = (__nv_bfloat16*)p;

    cudaFuncSetAttribute(gemm_mma, cudaFuncAttributeMaxDynamicSharedMemorySize, SMEM_GEMM);

    const int nTiles = (N + 127) / 128;
    const int Ntot = N + 1;
    const int nScanB = (Ntot + 1023) / 1024;

    cudaEventRecord(g_e1, 0);

    // ---- default stream: converts + gemm0 ----
    {
        dim3 g((128 * 256 + 255) / 256, 4);
        wconvert_all<<<g, 256>>>(lin_w0, agg_w0, lin_w1, agg_w1, wt);
    }
    xconvert_kernel<<<(N * 32 + 255) / 256, 256>>>(x, xb, N * 32);
    gemm_mma<<<nTiles, 256, SMEM_GEMM>>>(xb, nullptr, wt, 128, lin_b0,
                                         yb, nullptr, nullptr, N, 0);

    // ---- stream 2: CSR build + zero pool (independent) ----
    cudaStreamWaitEvent(g_s2, g_e1, 0);
    zero_cnt_kernel<<<(Ntot + 255) / 256, 256, 0, g_s2>>>(cnt, Ntot);
    hist_kernel<<<(E + 255) / 256, 256, 0, g_s2>>>(dst, cnt, E);
    scan1_kernel<<<nScanB, 1024, 0, g_s2>>>(cnt, bsum, Ntot);
    scan2_kernel<<<1, 32, 0, g_s2>>>(bsum, nScanB);
    scan3_kernel<<<nScanB, 1024, 0, g_s2>>>(cnt, bsum, off, fill, Ntot, N);
    fill_kernel<<<(E + 255) / 256, 256, 0, g_s2>>>(src, dst, fill, srcs, E);
    zero_pool_kernel<<<(NGRAPH * HID + 255) / 256, 256, 0, g_s2>>>(pooled, NGRAPH * HID);
    cudaEventRecord(g_e2, g_s2);

    cudaStreamWaitEvent(0, g_e2, 0);

    // layer 0
    agg_kernel<<<(N + 7) / 8, 256>>>(yb, aggb, off, srcs, N);
    gemm_mma<<<nTiles, 256, SMEM_GEMM>>>(aggb, xb, wt + 16384, 256, agg_b0,
                                         h0b, nullptr, nullptr, N, 1);
    // layer 1
    gemm_mma<<<nTiles, 256, SMEM_GEMM>>>(h0b, nullptr, wt + 49152, 128, lin_b1,
                                         yb, nullptr, nullptr, N, 0);
    agg_kernel<<<(N + 7) / 8, 256>>>(yb, aggb, off, srcs, N);
    gemm_mma<<<nTiles, 256, SMEM_GEMM>>>(aggb, h0b, wt + 65536, 256, agg_b1,
                                         nullptr, batch, pooled, N, 1);

    head_kernel<<<1, 256>>>(pooled, mp_w1, mp_b1, mp_w2, mp_b2, out);
}

// round 16
// speedup vs baseline: 1.0815x; 1.0039x over previous
#include <cuda_runtime.h>
#include <cuda_bf16.h>
#include <math.h>

#define MAXN 50000
#define MAXE 600000
#define HID 128
#define NGRAPH 64

// ---------------- scratch (static device globals) ----------------
__device__ __nv_bfloat16 g_xb[(size_t)MAXN * HID];
__device__ __nv_bfloat16 g_yb[(size_t)MAXN * HID];
__device__ __nv_bfloat16 g_h0b[(size_t)MAXN * HID];
__device__ __nv_bfloat16 g_aggb[(size_t)MAXN * HID];
__device__ int   g_cnt[MAXN + 1];
__device__ int   g_off[MAXN + 1];
__device__ int   g_fill[MAXN];
__device__ int   g_srcs[MAXE];
__device__ int   g_bsum[64];
__device__ float g_pooled[NGRAPH * HID];
__device__ __nv_bfloat16 g_wt[128 * 768];

// ---------------- tiny helpers ----------------
__device__ __forceinline__ void cpa16(unsigned dst, const void* src, int pbytes) {
    asm volatile("cp.async.cg.shared.global [%0], [%1], 16, %2;\n"
                 :: "r"(dst), "l"(src), "r"(pbytes));
}
__device__ __forceinline__ void cpa_commit() { asm volatile("cp.async.commit_group;\n"); }
__device__ __forceinline__ void cpa_wait0()  { asm volatile("cp.async.wait_group 0;\n"); }

__device__ __forceinline__ void mma16816(float c[4], const unsigned a[4], const unsigned* b) {
    asm volatile(
        "mma.sync.aligned.m16n8k16.row.col.f32.bf16.bf16.f32 "
        "{%0,%1,%2,%3},{%4,%5,%6,%7},{%8,%9},{%0,%1,%2,%3};"
        : "+f"(c[0]), "+f"(c[1]), "+f"(c[2]), "+f"(c[3])
        : "r"(a[0]), "r"(a[1]), "r"(a[2]), "r"(a[3]), "r"(b[0]), "r"(b[1]));
}
__device__ __forceinline__ void ldsm_x4(unsigned r[4], unsigned addr) {
    asm volatile("ldmatrix.sync.aligned.m8n8.x4.shared.b16 {%0,%1,%2,%3}, [%4];"
                 : "=r"(r[0]), "=r"(r[1]), "=r"(r[2]), "=r"(r[3]) : "r"(addr));
}

// ---------------- conversion kernels ----------------
__global__ void wconvert_all(const float* __restrict__ w0, const float* __restrict__ wa0,
                             const float* __restrict__ w1, const float* __restrict__ wa1,
                             __nv_bfloat16* __restrict__ wt)
{
    const int r = blockIdx.y;
    const int K   = (r & 1) ? 256 : 128;
    const int off = (r == 0) ? 0 : (r == 1) ? 16384 : (r == 2) ? 49152 : 65536;
    const float* W = (r == 0) ? w0 : (r == 1) ? wa0 : (r == 2) ? w1 : wa1;
    int idx = blockIdx.x * blockDim.x + threadIdx.x;
    if (idx >= 128 * K) return;
    int n = idx / K, k = idx % K;
    wt[off + idx] = __float2bfloat16(W[(size_t)k * 128 + n]);
}

__global__ void xconvert_kernel(const float* __restrict__ x,
                                __nv_bfloat16* __restrict__ xb, int total4)
{
    int i = blockIdx.x * blockDim.x + threadIdx.x;
    if (i >= total4) return;
    float4 v = *(const float4*)(x + (size_t)i * 4);
    __nv_bfloat162 p0(__float2bfloat16(v.x), __float2bfloat16(v.y));
    __nv_bfloat162 p1(__float2bfloat16(v.z), __float2bfloat16(v.w));
    *(__nv_bfloat162*)(xb + (size_t)i * 4)     = p0;
    *(__nv_bfloat162*)(xb + (size_t)i * 4 + 2) = p1;
}

// ---------------- CSR build ----------------
__global__ void zero_kernel(int* cnt, float* pooled, int ncnt, int npool) {
    int i = blockIdx.x * blockDim.x + threadIdx.x;
    if (i < ncnt)  cnt[i] = 0;
    if (i < npool) pooled[i] = 0.0f;
}
__global__ void hist_kernel(const int* __restrict__ dst, int* __restrict__ cnt, int E) {
    int e = blockIdx.x * blockDim.x + threadIdx.x;
    if (e < E) atomicAdd(&cnt[dst[e]], 1);
}
__global__ void scan1_kernel(const int* __restrict__ cnt, int* __restrict__ bsum, int Ntot) {
    __shared__ int ws[32];
    int i = blockIdx.x * 1024 + threadIdx.x;
    int v = (i < Ntot) ? cnt[i] : 0;
    #pragma unroll
    for (int d = 16; d > 0; d >>= 1) v += __shfl_down_sync(0xffffffffu, v, d);
    if ((threadIdx.x & 31) == 0) ws[threadIdx.x >> 5] = v;
    __syncthreads();
    if (threadIdx.x < 32) {
        int s = ws[threadIdx.x];
        #pragma unroll
        for (int d = 16; d > 0; d >>= 1) s += __shfl_down_sync(0xffffffffu, s, d);
        if (threadIdx.x == 0) bsum[blockIdx.x] = s;
    }
}
__global__ void scan2_kernel(int* __restrict__ bsum, int nb) {
    int tid = threadIdx.x;
    int v0 = (tid < nb) ? bsum[tid] : 0;
    int v1 = (tid + 32 < nb) ? bsum[tid + 32] : 0;
    int x = v0;
    #pragma unroll
    for (int d = 1; d < 32; d <<= 1) {
        int t = __shfl_up_sync(0xffffffffu, x, d);
        if (tid >= d) x += t;
    }
    int total0 = __shfl_sync(0xffffffffu, x, 31);
    int y = v1;
    #pragma unroll
    for (int d = 1; d < 32; d <<= 1) {
        int t = __shfl_up_sync(0xffffffffu, y, d);
        if (tid >= d) y += t;
    }
    if (tid < nb) bsum[tid] = x - v0;
    if (tid + 32 < nb) bsum[tid + 32] = total0 + y - v1;
}
__global__ void scan3_kernel(const int* __restrict__ cnt, const int* __restrict__ bsum,
                             int* __restrict__ off, int* __restrict__ fill, int Ntot, int N) {
    __shared__ int ws[32];
    int i = blockIdx.x * 1024 + threadIdx.x;
    int tid = threadIdx.x;
    int v = (i < Ntot) ? cnt[i] : 0;
    int x = v;
    #pragma unroll
    for (int d = 1; d < 32; d <<= 1) {
        int t = __shfl_up_sync(0xffffffffu, x, d);
        if ((tid & 31) >= d) x += t;
    }
    if ((tid & 31) == 31) ws[tid >> 5] = x;
    __syncthreads();
    if (tid < 32) {
        int w = ws[tid];
        #pragma unroll
        for (int d = 1; d < 32; d <<= 1) {
            int t = __shfl_up_sync(0xffffffffu, w, d);
            if (tid >= d) w += t;
        }
        ws[tid] = w;
    }
    __syncthreads();
    int warpOff = (tid >= 32) ? ws[(tid >> 5) - 1] : 0;
    int excl = bsum[blockIdx.x] + warpOff + x - v;
    if (i < Ntot) {
        off[i] = excl;
        if (i < N) fill[i] = excl;
    }
}
__global__ void fill_kernel(const int* __restrict__ src, const int* __restrict__ dst,
                            int* __restrict__ fill, int* __restrict__ srcs, int E) {
    int e = blockIdx.x * blockDim.x + threadIdx.x;
    if (e < E) {
        int p = atomicAdd(&fill[dst[e]], 1);
        srcs[p] = src[e];
    }
}

// ---------------- GEMM: single-pass bf16, 64-k chunks, fused pool --------
// K=128: both chunks staged upfront, single wait/barrier, barrier-free compute.
// K=256: 2-stage pipelined loop.
#define APAD 72
#define STG_ELEMS (2 * 128 * APAD)
#define POOL_SPAN 4
#define SMEM_GEMM (2 * STG_ELEMS * 2 + 1024 + POOL_SPAN * 128 * 4)

__device__ __forceinline__ void stage_chunk(
    const __nv_bfloat16* __restrict__ A1, const __nv_bfloat16* __restrict__ A2,
    const __nv_bfloat16* __restrict__ wt,
    int Ktot, unsigned sbase, int kg, int rowBase, int M, int tid)
{
    const __nv_bfloat16* A = (kg < 128) ? A1 : A2;
    const int kk = (kg < 128) ? kg : kg - 128;
    #pragma unroll
    for (int p = 0; p < 4; ++p) {
        int idx = p * 256 + tid;
        int row = idx >> 3, seg = idx & 7;
        int g = rowBase + row;
        int pb = (g < M) ? 16 : 0;
        int gc = (g < M) ? g : 0;
        cpa16(sbase + (row * APAD + seg * 8) * 2,
              A + (size_t)gc * 128 + kk + seg * 8, pb);
    }
    #pragma unroll
    for (int p = 0; p < 4; ++p) {
        int idx = p * 256 + tid;
        int n = idx >> 3, seg = idx & 7;
        cpa16(sbase + (128 * APAD + n * APAD + seg * 8) * 2,
              wt + (size_t)n * Ktot + kg + seg * 8, 16);
    }
}

__global__ __launch_bounds__(256, 2)
void gemm_mma(const __nv_bfloat16* __restrict__ A1, const __nv_bfloat16* __restrict__ A2,
              const __nv_bfloat16* __restrict__ wt,
              int Ktot, const float* __restrict__ bias,
              __nv_bfloat16* __restrict__ C,
              const int* __restrict__ batch, float* __restrict__ pooled,
              int M, int doNorm)
{
    extern __shared__ __align__(16) __nv_bfloat16 smem[];
    float* rowss = (float*)(smem + 2 * STG_ELEMS);
    float* spool = rowss + 256;
    const unsigned sb = (unsigned)__cvta_generic_to_shared(smem);

    const int tid = threadIdx.x;
    const int wid = tid >> 5, lane = tid & 31;
    const int wm = wid & 3, wn = wid >> 2;
    const int g4 = lane >> 2, q = lane & 3;
    const int rowBase = blockIdx.x * 128;

    const int aRow = wm * 32 + (lane & 15);
    const int aCol = (lane & 16) ? 8 : 0;
    const unsigned aAddr0 = sb + (unsigned)(aRow * APAD + aCol) * 2;
    const int bRow = wn * 64 + (lane & 7) + ((lane & 16) ? 8 : 0);
    const int bCol = (lane & 8) ? 8 : 0;
    const unsigned bAddr0 = sb + (unsigned)(128 * APAD + bRow * APAD + bCol) * 2;
    const unsigned I16 = 16 * APAD * 2;
    const int nChunks = Ktot / 64;

    float acc[2][8][4];
    #pragma unroll
    for (int i = 0; i < 2; ++i)
        #pragma unroll
        for (int j = 0; j < 8; ++j)
            #pragma unroll
            for (int v = 0; v < 4; ++v) acc[i][j][v] = 0.0f;

    if (Ktot == 128) {
        // single-phase: stage both chunks, one wait, one barrier, no mid barriers
        stage_chunk(A1, A2, wt, 128, sb, 0, rowBase, M, tid);
        stage_chunk(A1, A2, wt, 128, sb + STG_ELEMS * 2, 64, rowBase, M, tid);
        cpa_commit();
        cpa_wait0();
        __syncthreads();
        #pragma unroll
        for (int kc = 0; kc < 2; ++kc) {
            const unsigned stoff = (unsigned)kc * STG_ELEMS * 2;
            #pragma unroll
            for (int k16 = 0; k16 < 4; ++k16) {
                const unsigned kb = (unsigned)k16 * 32;
                unsigned a0[4], a1[4];
                ldsm_x4(a0, aAddr0 + stoff + kb);
                ldsm_x4(a1, aAddr0 + stoff + kb + I16);
                unsigned bh[4][4];
                #pragma unroll
                for (int jj = 0; jj < 4; ++jj)
                    ldsm_x4(bh[jj], bAddr0 + stoff + kb + (unsigned)jj * I16);
                #pragma unroll
                for (int jj = 0; jj < 4; ++jj) {
                    mma16816(acc[0][2 * jj],     a0, &bh[jj][0]);
                    mma16816(acc[1][2 * jj],     a1, &bh[jj][0]);
                    mma16816(acc[0][2 * jj + 1], a0, &bh[jj][2]);
                    mma16816(acc[1][2 * jj + 1], a1, &bh[jj][2]);
                }
            }
        }
    } else {
        stage_chunk(A1, A2, wt, Ktot, sb, 0, rowBase, M, tid);
        cpa_commit();
        for (int kc = 0; kc < nChunks; ++kc) {
            cpa_wait0();
            __syncthreads();
            if (kc + 1 < nChunks) {
                stage_chunk(A1, A2, wt, Ktot,
                            sb + ((kc + 1) & 1) * STG_ELEMS * 2, (kc + 1) * 64, rowBase, M, tid);
                cpa_commit();
            }
            const unsigned stoff = ((unsigned)(kc & 1)) * STG_ELEMS * 2;
            #pragma unroll
            for (int k16 = 0; k16 < 4; ++k16) {
                const unsigned kb = (unsigned)k16 * 32;
                unsigned a0[4], a1[4];
                ldsm_x4(a0, aAddr0 + stoff + kb);
                ldsm_x4(a1, aAddr0 + stoff + kb + I16);
                unsigned bh[4][4];
                #pragma unroll
                for (int jj = 0; jj < 4; ++jj)
                    ldsm_x4(bh[jj], bAddr0 + stoff + kb + (unsigned)jj * I16);
                #pragma unroll
                for (int jj = 0; jj < 4; ++jj) {
                    mma16816(acc[0][2 * jj],     a0, &bh[jj][0]);
                    mma16816(acc[1][2 * jj],     a1, &bh[jj][0]);
                    mma16816(acc[0][2 * jj + 1], a0, &bh[jj][2]);
                    mma16816(acc[1][2 * jj + 1], a1, &bh[jj][2]);
                }
            }
        }
    }

    #pragma unroll
    for (int j = 0; j < 8; ++j) {
        int col = wn * 64 + j * 8 + q * 2;
        float2 b = *(const float2*)(bias + col);
        #pragma unroll
        for (int i = 0; i < 2; ++i) {
            acc[i][j][0] = fmaxf(acc[i][j][0] + b.x, 0.0f);
            acc[i][j][1] = fmaxf(acc[i][j][1] + b.y, 0.0f);
            acc[i][j][2] = fmaxf(acc[i][j][2] + b.x, 0.0f);
            acc[i][j][3] = fmaxf(acc[i][j][3] + b.y, 0.0f);
        }
    }
    if (doNorm) {
        __syncthreads();
        #pragma unroll
        for (int i = 0; i < 2; ++i) {
            int r = wm * 32 + i * 16 + g4;
            float ssLo = 0.f, ssHi = 0.f;
            #pragma unroll
            for (int j = 0; j < 8; ++j) {
                ssLo += acc[i][j][0] * acc[i][j][0] + acc[i][j][1] * acc[i][j][1];
                ssHi += acc[i][j][2] * acc[i][j][2] + acc[i][j][3] * acc[i][j][3];
            }
            ssLo += __shfl_xor_sync(0xffffffffu, ssLo, 1);
            ssLo += __shfl_xor_sync(0xffffffffu, ssLo, 2);
            ssHi += __shfl_xor_sync(0xffffffffu, ssHi, 1);
            ssHi += __shfl_xor_sync(0xffffffffu, ssHi, 2);
            if (q == 0) { rowss[r * 2 + wn] = ssLo; rowss[(r + 8) * 2 + wn] = ssHi; }
        }
        __syncthreads();
        #pragma unroll
        for (int i = 0; i < 2; ++i) {
            int r = wm * 32 + i * 16 + g4;
            float invLo = 1.0f / fmaxf(sqrtf(rowss[r * 2] + rowss[r * 2 + 1]), 1e-12f);
            float invHi = 1.0f / fmaxf(sqrtf(rowss[(r + 8) * 2] + rowss[(r + 8) * 2 + 1]), 1e-12f);
            #pragma unroll
            for (int j = 0; j < 8; ++j) {
                acc[i][j][0] *= invLo; acc[i][j][1] *= invLo;
                acc[i][j][2] *= invHi; acc[i][j][3] *= invHi;
            }
        }
    }

    if (pooled) {
        for (int s = tid; s < POOL_SPAN * 128; s += 256) spool[s] = 0.0f;
        __syncthreads();
        const int gLo = batch[rowBase];
        #pragma unroll
        for (int i = 0; i < 2; ++i) {
            int r0 = rowBase + wm * 32 + i * 16 + g4;
            int r1 = r0 + 8;
            int dg0 = (r0 < M) ? (batch[r0] - gLo) : -1;
            int dg1 = (r1 < M) ? (batch[r1] - gLo) : -1;
            #pragma unroll
            for (int j = 0; j < 8; ++j) {
                int col = wn * 64 + j * 8 + q * 2;
                if (dg0 >= 0) {
                    if (dg0 < POOL_SPAN) {
                        atomicMax((int*)&spool[dg0 * 128 + col],     __float_as_int(acc[i][j][0]));
                        atomicMax((int*)&spool[dg0 * 128 + col + 1], __float_as_int(acc[i][j][1]));
                    } else {
                        atomicMax((int*)&pooled[(gLo + dg0) * 128 + col],     __float_as_int(acc[i][j][0]));
                        atomicMax((int*)&pooled[(gLo + dg0) * 128 + col + 1], __float_as_int(acc[i][j][1]));
                    }
                }
                if (dg1 >= 0) {
                    if (dg1 < POOL_SPAN) {
                        atomicMax((int*)&spool[dg1 * 128 + col],     __float_as_int(acc[i][j][2]));
                        atomicMax((int*)&spool[dg1 * 128 + col + 1], __float_as_int(acc[i][j][3]));
                    } else {
                        atomicMax((int*)&pooled[(gLo + dg1) * 128 + col],     __float_as_int(acc[i][j][2]));
                        atomicMax((int*)&pooled[(gLo + dg1) * 128 + col + 1], __float_as_int(acc[i][j][3]));
                    }
                }
            }
        }
        __syncthreads();
        for (int s = tid; s < POOL_SPAN * 128; s += 256) {
            float v = spool[s];
            int gIdx = gLo + (s >> 7);
            if (v > 0.0f && gIdx < NGRAPH)
                atomicMax((int*)&pooled[gIdx * 128 + (s & 127)], __float_as_int(v));
        }
    } else {
        #pragma unroll
        for (int i = 0; i < 2; ++i) {
            int r0 = rowBase + wm * 32 + i * 16 + g4;
            #pragma unroll
            for (int j = 0; j < 8; ++j) {
                int col = wn * 64 + j * 8 + q * 2;
                __nv_bfloat162 p0(__float2bfloat16(acc[i][j][0]), __float2bfloat16(acc[i][j][1]));
                __nv_bfloat162 p1(__float2bfloat16(acc[i][j][2]), __float2bfloat16(acc[i][j][3]));
                if (r0 < M)
                    *(__nv_bfloat162*)(C + (size_t)r0 * 128 + col) = p0;
                if (r0 + 8 < M)
                    *(__nv_bfloat162*)(C + (size_t)(r0 + 8) * 128 + col) = p1;
            }
        }
    }
}

// ---------------- CSR mean aggregation: 4-way unrolled gather ----------------
__global__ void agg_kernel(const __nv_bfloat16* __restrict__ y,
                           __nv_bfloat16* __restrict__ agg,
                           const int* __restrict__ off, const int* __restrict__ srcs,
                           int N)
{
    int w = (blockIdx.x * blockDim.x + threadIdx.x) >> 5;
    int lane = threadIdx.x & 31;
    if (w >= N) return;
    int s0 = off[w], s1 = off[w + 1];
    float acc0 = 0.f, acc1 = 0.f, acc2 = 0.f, acc3 = 0.f;
    int i = s0;
    for (; i + 3 < s1; i += 4) {
        int sA = __ldg(&srcs[i]);
        int sB = __ldg(&srcs[i + 1]);
        int sC = __ldg(&srcs[i + 2]);
        int sD = __ldg(&srcs[i + 3]);
        uint2 hA = *(const uint2*)(y + (size_t)sA * 128 + lane * 4);
        uint2 hB = *(const uint2*)(y + (size_t)sB * 128 + lane * 4);
        uint2 hC = *(const uint2*)(y + (size_t)sC * 128 + lane * 4);
        uint2 hD = *(const uint2*)(y + (size_t)sD * 128 + lane * 4);
        float2 a, b;
        a = __bfloat1622float2(*(const __nv_bfloat162*)&hA.x);
        b = __bfloat1622float2(*(const __nv_bfloat162*)&hA.y);
        acc0 += a.x; acc1 += a.y; acc2 += b.x; acc3 += b.y;
        a = __bfloat1622float2(*(const __nv_bfloat162*)&hB.x);
        b = __bfloat1622float2(*(const __nv_bfloat162*)&hB.y);
        acc0 += a.x; acc1 += a.y; acc2 += b.x; acc3 += b.y;
        a = __bfloat1622float2(*(const __nv_bfloat162*)&hC.x);
        b = __bfloat1622float2(*(const __nv_bfloat162*)&hC.y);
        acc0 += a.x; acc1 += a.y; acc2 += b.x; acc3 += b.y;
        a = __bfloat1622float2(*(const __nv_bfloat162*)&hD.x);
        b = __bfloat1622float2(*(const __nv_bfloat162*)&hD.y);
        acc0 += a.x; acc1 += a.y; acc2 += b.x; acc3 += b.y;
    }
    for (; i < s1; ++i) {
        int sA = __ldg(&srcs[i]);
        uint2 hA = *(const uint2*)(y + (size_t)sA * 128 + lane * 4);
        float2 a = __bfloat1622float2(*(const __nv_bfloat162*)&hA.x);
        float2 b = __bfloat1622float2(*(const __nv_bfloat162*)&hA.y);
        acc0 += a.x; acc1 += a.y; acc2 += b.x; acc3 += b.y;
    }
    float inv = 1.0f / fmaxf((float)(s1 - s0), 1.0f);
    __nv_bfloat162 p0(__float2bfloat16(acc0 * inv), __float2bfloat16(acc1 * inv));
    __nv_bfloat162 p1(__float2bfloat16(acc2 * inv), __float2bfloat16(acc3 * inv));
    *(__nv_bfloat162*)(agg + (size_t)w * 128 + lane * 4)     = p0;
    *(__nv_bfloat162*)(agg + (size_t)w * 128 + lane * 4 + 2) = p1;
}

// ---------------- head ----------------
__global__ void head_kernel(const float* __restrict__ pooled,
                            const float* __restrict__ w1, const float* __restrict__ b1,
                            const float* __restrict__ w2, const float* __restrict__ b2,
                            float* __restrict__ out)
{
    __shared__ float t[NGRAPH][HID];
    int tid = threadIdx.x;
    for (int o = tid; o < NGRAPH * HID; o += blockDim.x) {
        int r = o >> 7, c = o & 127;
        float s = b1[c];
        #pragma unroll 8
        for (int k = 0; k < 128; ++k) s = fmaf(pooled[r * 128 + k], w1[k * 128 + c], s);
        t[r][c] = s;
    }
    __syncthreads();
    if (tid < NGRAPH) {
        float z0 = b2[0], z1 = b2[1];
        #pragma unroll 8
        for (int k = 0; k < 128; ++k) {
            float v = t[tid][k];
            z0 = fmaf(v, w2[k * 2 + 0], z0);
            z1 = fmaf(v, w2[k * 2 + 1], z1);
        }
        float m = fmaxf(z0, z1);
        float lse = m + logf(expf(z0 - m) + expf(z1 - m));
        out[tid * 2 + 0] = z0 - lse;
        out[tid * 2 + 1] = z1 - lse;
    }
}

// ---------------- launch ----------------
static cudaStream_t g_s2 = nullptr;
static cudaEvent_t  g_e1 = nullptr, g_e2 = nullptr;

extern "C" void kernel_launch(void* const* d_in, const int* in_sizes, int n_in,
                              void* d_out, int out_size)
{
    const float* x      = (const float*)d_in[0];
    const int*   ei     = (const int*)  d_in[1];
    const int*   batch  = (const int*)  d_in[2];
    const float* lin_w0 = (const float*)d_in[3];
    const float* lin_b0 = (const float*)d_in[4];
    const float* agg_w0 = (const float*)d_in[5];
    const float* agg_b0 = (const float*)d_in[6];
    const float* lin_w1 = (const float*)d_in[7];
    const float* lin_b1 = (const float*)d_in[8];
    const float* agg_w1 = (const float*)d_in[9];
    const float* agg_b1 = (const float*)d_in[10];
    const float* mp_w1  = (const float*)d_in[11];
    const float* mp_b1  = (const float*)d_in[12];
    const float* mp_w2  = (const float*)d_in[13];
    const float* mp_b2  = (const float*)d_in[14];
    float* out = (float*)d_out;

    const int N = in_sizes[0] / HID;
    const int E = in_sizes[1] / 2;
    const int* src = ei;
    const int* dst = ei + E;

    if (!g_s2) {
        cudaStreamCreateWithFlags(&g_s2, cudaStreamNonBlocking);
        cudaEventCreateWithFlags(&g_e1, cudaEventDisableTiming);
        cudaEventCreateWithFlags(&g_e2, cudaEventDisableTiming);
    }

    void *p;
    float *pooled;
    int *cnt, *off, *fill, *srcs, *bsum;
    __nv_bfloat16 *xb, *yb, *h0b, *aggb, *wt;
    cudaGetSymbolAddress(&p, g_pooled); pooled = (float*)p;
    cudaGetSymbolAddress(&p, g_cnt);    cnt    = (int*)p;
    cudaGetSymbolAddress(&p, g_off);    off    = (int*)p;
    cudaGetSymbolAddress(&p, g_fill);   fill   = (int*)p;
    cudaGetSymbolAddress(&p, g_srcs);   srcs   = (int*)p;
    cudaGetSymbolAddress(&p, g_bsum);   bsum   = (int*)p;
    cudaGetSymbolAddress(&p, g_xb);     xb     = (__nv_bfloat16*)p;
    cudaGetSymbolAddress(&p, g_yb);     yb     = (__nv_bfloat16*)p;
    cudaGetSymbolAddress(&p, g_h0b);    h0b    = (__nv_bfloat16*)p;
    cudaGetSymbolAddress(&p, g_aggb);   aggb   = (__nv_bfloat16*)p;
    cudaGetSymbolAddress(&p, g_wt);     wt     = (__nv_bfloat16*)p;

    cudaFuncSetAttribute(gemm_mma, cudaFuncAttributeMaxDynamicSharedMemorySize, SMEM_GEMM);

    const int nTiles = (N + 127) / 128;
    const int Ntot = N + 1;
    const int nScanB = (Ntot + 1023) / 1024;
    const int zeroN = (Ntot > NGRAPH * HID) ? Ntot : NGRAPH * HID;

    cudaEventRecord(g_e1, 0);

    // ---- default stream: converts + gemm0 ----
    {
        dim3 g((128 * 256 + 255) / 256, 4);
        wconvert_all<<<g, 256>>>(lin_w0, agg_w0, lin_w1, agg_w1, wt);
    }
    xconvert_kernel<<<(N * 32 + 255) / 256, 256>>>(x, xb, N * 32);
    gemm_mma<<<nTiles, 256, SMEM_GEMM>>>(xb, nullptr, wt, 128, lin_b0,
                                         yb, nullptr, nullptr, N, 0);

    // ---- stream 2: CSR build + zero pool (merged zeros) ----
    cudaStreamWaitEvent(g_s2, g_e1, 0);
    zero_kernel<<<(zeroN + 255) / 256, 256, 0, g_s2>>>(cnt, pooled, Ntot, NGRAPH * HID);
    hist_kernel<<<(E + 255) / 256, 256, 0, g_s2>>>(dst, cnt, E);
    scan1_kernel<<<nScanB, 1024, 0, g_s2>>>(cnt, bsum, Ntot);
    scan2_kernel<<<1, 32, 0, g_s2>>>(bsum, nScanB);
    scan3_kernel<<<nScanB, 1024, 0, g_s2>>>(cnt, bsum, off, fill, Ntot, N);
    fill_kernel<<<(E + 255) / 256, 256, 0, g_s2>>>(src, dst, fill, srcs, E);
    cudaEventRecord(g_e2, g_s2);

    cudaStreamWaitEvent(0, g_e2, 0);

    // layer 0
    agg_kernel<<<(N + 7) / 8, 256>>>(yb, aggb, off, srcs, N);
    gemm_mma<<<nTiles, 256, SMEM_GEMM>>>(aggb, xb, wt + 16384, 256, agg_b0,
                                         h0b, nullptr, nullptr, N, 1);
    // layer 1
    gemm_mma<<<nTiles, 256, SMEM_GEMM>>>(h0b, nullptr, wt + 49152, 128, lin_b1,
                                         yb, nullptr, nullptr, N, 0);
    agg_kernel<<<(N + 7) / 8, 256>>>(yb, aggb, off, srcs, N);
    gemm_mma<<<nTiles, 256, SMEM_GEMM>>>(aggb, h0b, wt + 65536, 256, agg_b1,
                                         nullptr, batch, pooled, N, 1);

    head_kernel<<<1, 256>>>(pooled, mp_w1, mp_b1, mp_w2, mp_b2, out);
}